// round 4
// baseline (speedup 1.0000x reference)
#include <cuda_runtime.h>
#include <cstdint>

typedef unsigned long long ull;

#define CCH 12
#define LL 8192
#define NB 512
#define LT 1024
#define HALO 160
#define TILEW (LT + 2*HALO)      // 1344
#define NCP 6                    // channel pairs
#define PP 4                     // outputs per thread per group pass
#define NTH 256
#define NTILES (LL/LT)           // 8
#define NF 90

// Per-(n, filter, tile) partials: x = count(conv+b > 0), y = max(conv+b)
__device__ float2 g_part[NB * NF * NTILES];

// XOR swizzle over 8B shared slots: 16 slots per 128B bank row.
// sw = (row ^ ((row&2)<<2)) & 15 gives the optimal 2-phase LDS.64 pattern
// for every dilation stride d in {1,2,4,8,16,32} with P=4 chains.
__device__ __forceinline__ uint32_t swz(uint32_t idx){
    uint32_t row = idx >> 4;
    uint32_t sw = (row ^ ((row & 2u) << 2)) & 15u;
    return idx ^ sw;
}

__device__ __forceinline__ ull pack2(float lo, float hi){
    ull r; asm("mov.b64 %0, {%1, %2};" : "=l"(r) : "f"(lo), "f"(hi)); return r;
}
__device__ __forceinline__ void unpack2(ull v, float& lo, float& hi){
    asm("mov.b64 {%0, %1}, %2;" : "=f"(lo), "=f"(hi) : "l"(v));
}
// Packed dual fp32 FMA (FFMA2) — full 128-lane fp32 datapath, exact fp32 rounding.
__device__ __forceinline__ ull fma2(ull a, ull b, ull c){
    ull d; asm("fma.rn.f32x2 %0, %1, %2, %3;" : "=l"(d) : "l"(a), "l"(b), "l"(c)); return d;
}

template<int K>
__device__ __forceinline__ void do_group(
    const ull* __restrict__ xs, const ull* __restrict__ ws,
    const float* __restrict__ bias_s, float* red,
    int dlog, int n, int fid_base, int tile)
{
    const int t = threadIdx.x;
    const int d = 1 << dlog;
    const int hk = (K - 1) / 2;
    const int r  = t & (d - 1);
    const int p0 = r + (((t >> dlog) * PP) << dlog);  // chain base position in tile
    const int base0 = HALO + p0 - hk * d;             // first tap of first output

    ull acc[5][PP];
    #pragma unroll
    for (int f = 0; f < 5; f++)
        #pragma unroll
        for (int i = 0; i < PP; i++) acc[f][i] = 0ull;

    #pragma unroll 1
    for (int cp = 0; cp < NCP; cp++){
        // shared window of P+K-1 channel-pair values, stride d (dilated-chain reuse)
        ull xw[PP + K - 1];
        const int b = cp * TILEW + base0;
        #pragma unroll
        for (int j = 0; j < PP + K - 1; j++) xw[j] = xs[swz((uint32_t)(b + j * d))];

        const ull* wbase = ws + cp * K * 6;
        #pragma unroll
        for (int k = 0; k < K; k++){
            const ull* wrow = wbase + k * 6;            // 16B-aligned row of 5 packed weights
            ulonglong2 w01 = *(const ulonglong2*)(wrow);
            ulonglong2 w23 = *(const ulonglong2*)(wrow + 2);
            ull        w4  = wrow[4];
            #pragma unroll
            for (int i = 0; i < PP; i++){
                ull xv = xw[i + k];
                acc[0][i] = fma2(xv, w01.x, acc[0][i]);
                acc[1][i] = fma2(xv, w01.y, acc[1][i]);
                acc[2][i] = fma2(xv, w23.x, acc[2][i]);
                acc[3][i] = fma2(xv, w23.y, acc[3][i]);
                acc[4][i] = fma2(xv, w4,    acc[4][i]);
            }
        }
    }

    // Epilogue: conv = lo+hi (+bias), ppv-count and max per filter
    int cnt[5]; float mx[5];
    #pragma unroll
    for (int f = 0; f < 5; f++){ cnt[f] = 0; mx[f] = __int_as_float(0xff800000); }
    #pragma unroll
    for (int f = 0; f < 5; f++){
        float bb = bias_s[f];
        #pragma unroll
        for (int i = 0; i < PP; i++){
            float lo, hi; unpack2(acc[f][i], lo, hi);
            float v = lo + hi + bb;
            cnt[f] += (v > 0.0f) ? 1 : 0;
            mx[f] = fmaxf(mx[f], v);
        }
    }
    // warp reduce
    #pragma unroll
    for (int off = 16; off > 0; off >>= 1){
        #pragma unroll
        for (int f = 0; f < 5; f++){
            cnt[f] += __shfl_xor_sync(0xffffffffu, cnt[f], off);
            mx[f]   = fmaxf(mx[f], __shfl_xor_sync(0xffffffffu, mx[f], off));
        }
    }
    const int lane = t & 31, w = t >> 5;
    if (lane < 5){
        red[(w * 5 + lane) * 2 + 0] = (float)cnt[lane];
        red[(w * 5 + lane) * 2 + 1] = mx[lane];
    }
    __syncthreads();
    if (t < 5){
        float cs = 0.0f, m = __int_as_float(0xff800000);
        #pragma unroll
        for (int wi = 0; wi < NTH/32; wi++){
            cs += red[(wi * 5 + t) * 2 + 0];
            m = fmaxf(m, red[(wi * 5 + t) * 2 + 1]);
        }
        g_part[(n * NF + fid_base + t) * NTILES + tile] = make_float2(cs, m);
    }
}

__global__ void __launch_bounds__(NTH, 1) rocket_conv_kernel(
    const float* __restrict__ x,
    const float* __restrict__ W7,  const float* __restrict__ b7,
    const float* __restrict__ W9,  const float* __restrict__ b9,
    const float* __restrict__ W11, const float* __restrict__ b11)
{
    extern __shared__ ull sm[];
    ull*   xs     = sm;                              // NCP*TILEW = 8064 ull
    ull*   ws     = sm + NCP * TILEW;                // up to 6*11*6 = 396 ull
    float* red    = (float*)(ws + NCP * 11 * 6);     // 8 warps * 5 * 2
    float* bias_s = red + (NTH/32) * 5 * 2;          // 5 floats

    const int t    = threadIdx.x;
    const int tile = blockIdx.x;
    const int n    = blockIdx.y;
    const int t0   = tile * LT;

    // Fill channel-pair-packed, swizzled x tile (with SAME-padding halo = 160 each side)
    const float* xn = x + (size_t)n * CCH * LL;
    for (int idx = t; idx < NCP * TILEW; idx += NTH){
        int cp = idx / TILEW;
        int p  = idx - cp * TILEW;
        int l  = t0 + p - HALO;
        float lo = 0.0f, hi = 0.0f;
        if (l >= 0 && l < LL){
            lo = xn[(2*cp)     * LL + l];
            hi = xn[(2*cp + 1) * LL + l];
        }
        xs[swz((uint32_t)idx)] = pack2(lo, hi);
    }
    __syncthreads();

    for (int kidx = 0; kidx < 3; kidx++){
        const float* W    = (kidx == 0) ? W7 : (kidx == 1 ? W9 : W11);
        const float* bptr = (kidx == 0) ? b7 : (kidx == 1 ? b9 : b11);
        const int K = 7 + 2 * kidx;
        for (int j = 0; j < 6; j++){          // dilation = 1 << j
            const int fbase = j * 5;
            // Stage packed weights: ws[(cp*K + k)*6 + f] = {W[f][2cp][k], W[f][2cp+1][k]}
            for (int idx = t; idx < NCP * K * 5; idx += NTH){
                int cp = idx / (K * 5);
                int rr = idx - cp * K * 5;
                int k  = rr / 5;
                int f  = rr - k * 5;
                const float* wf = W + (size_t)(fbase + f) * CCH * K;
                float lo = wf[(2*cp)     * K + k];
                float hi = wf[(2*cp + 1) * K + k];
                ws[(cp * K + k) * 6 + f] = pack2(lo, hi);
            }
            if (t < 5) bias_s[t] = bptr[fbase + t];
            __syncthreads();

            const int fid_base = kidx * 30 + j * 5;
            if (K == 7)      do_group<7 >(xs, ws, bias_s, red, j, n, fid_base, tile);
            else if (K == 9) do_group<9 >(xs, ws, bias_s, red, j, n, fid_base, tile);
            else             do_group<11>(xs, ws, bias_s, red, j, n, fid_base, tile);
        }
    }
}

// Combine tile partials, batch-normalize, write (512,180) output.
// One block per feature column; two samples per thread.
__global__ void rocket_finalize_kernel(float* __restrict__ out)
{
    __shared__ float sb[NTH];
    const int col = blockIdx.x;             // 0..179
    const int t   = threadIdx.x;
    const int kidx = col / 60;
    const int rem  = col - kidx * 60;
    const int j    = rem / 10;
    const int p    = (rem % 10) >> 1;
    const int s    = col & 1;               // 0 = ppv, 1 = max
    const int fid  = kidx * 30 + j * 5 + p;

    float raw[2];
    #pragma unroll
    for (int e = 0; e < 2; e++){
        int n = t + e * NTH;
        const float2* pp = &g_part[(n * NF + fid) * NTILES];
        float cs = 0.0f, m = __int_as_float(0xff800000);
        #pragma unroll
        for (int tt = 0; tt < NTILES; tt++){
            float2 v = pp[tt];
            cs += v.x;
            m = fmaxf(m, v.y);
        }
        raw[e] = s ? m : cs * (1.0f / (float)LL);
    }

    // two-pass mean/var over the 512-sample batch (avoids E[x^2]-mu^2 cancellation)
    sb[t] = raw[0] + raw[1];
    __syncthreads();
    for (int stp = NTH/2; stp > 0; stp >>= 1){
        if (t < stp) sb[t] += sb[t + stp];
        __syncthreads();
    }
    float mean = sb[0] * (1.0f / (float)NB);
    __syncthreads();
    float d0 = raw[0] - mean, d1 = raw[1] - mean;
    sb[t] = d0*d0 + d1*d1;
    __syncthreads();
    for (int stp = NTH/2; stp > 0; stp >>= 1){
        if (t < stp) sb[t] += sb[t + stp];
        __syncthreads();
    }
    float var = sb[0] * (1.0f / (float)NB);
    float inv = rsqrtf(var + 1e-5f);
    out[(size_t)t * 180 + col]         = d0 * inv;
    out[(size_t)(t + NTH) * 180 + col] = d1 * inv;
}

extern "C" void kernel_launch(void* const* d_in, const int* in_sizes, int n_in,
                              void* d_out, int out_size)
{
    const float* x   = (const float*)d_in[0];
    const float* W7  = (const float*)d_in[1];
    const float* b7  = (const float*)d_in[2];
    const float* W9  = (const float*)d_in[3];
    const float* b9  = (const float*)d_in[4];
    const float* W11 = (const float*)d_in[5];
    const float* b11 = (const float*)d_in[6];
    float* out = (float*)d_out;

    const int SMEM_BYTES = (NCP * TILEW + NCP * 11 * 6) * 8   // xs + ws
                         + ((NTH/32) * 5 * 2 + 5) * 4 + 16;   // red + bias + pad
    cudaFuncSetAttribute(rocket_conv_kernel,
                         cudaFuncAttributeMaxDynamicSharedMemorySize, SMEM_BYTES);

    dim3 grid(NTILES, NB);
    rocket_conv_kernel<<<grid, NTH, SMEM_BYTES>>>(x, W7, b7, W9, b9, W11, b11);
    rocket_finalize_kernel<<<180, NTH>>>(out);
}

// round 5
// speedup vs baseline: 1.0003x; 1.0003x over previous
#include <cuda_runtime.h>
#include <cstdint>

typedef unsigned long long ull;

#define CCH 12
#define LL 8192
#define NB 512
#define LT 1024
#define HALO 160
#define TILEW (LT + 2*HALO)      // 1344
#define NCP 6                    // channel pairs
#define PP 4                     // outputs per thread per group pass
#define NTH 256
#define NTILES (LL/LT)           // 8
#define NF 90

// Per-(n, filter, tile) partials: x = count(conv+b > 0), y = max(conv+b)
__device__ float2 g_part[NB * NF * NTILES];

// XOR swizzle over 8B shared slots: 16 slots per 128B bank row.
// sw = (row ^ ((row&2)<<2)) & 15 gives the optimal 2-phase LDS.64 pattern
// for every dilation stride d in {1,2,4,8,16,32} with P=4 chains.
__device__ __forceinline__ uint32_t swz(uint32_t idx){
    uint32_t row = idx >> 4;
    uint32_t sw = (row ^ ((row & 2u) << 2)) & 15u;
    return idx ^ sw;
}

__device__ __forceinline__ ull pack2(float lo, float hi){
    ull r; asm("mov.b64 %0, {%1, %2};" : "=l"(r) : "f"(lo), "f"(hi)); return r;
}
__device__ __forceinline__ void unpack2(ull v, float& lo, float& hi){
    asm("mov.b64 {%0, %1}, %2;" : "=f"(lo), "=f"(hi) : "l"(v));
}
// Packed dual fp32 FMA (FFMA2) — full 128-lane fp32 datapath, exact fp32 rounding.
__device__ __forceinline__ ull fma2(ull a, ull b, ull c){
    ull d; asm("fma.rn.f32x2 %0, %1, %2, %3;" : "=l"(d) : "l"(a), "l"(b), "l"(c)); return d;
}

template<int K>
__device__ __forceinline__ void do_group(
    const ull* __restrict__ xs, const ull* __restrict__ ws,
    const float* __restrict__ bias_s, float* red,
    int dlog, int n, int fid_base, int tile)
{
    const int t = threadIdx.x;
    const int d = 1 << dlog;
    const int hk = (K - 1) / 2;
    const int r  = t & (d - 1);
    const int p0 = r + (((t >> dlog) * PP) << dlog);  // chain base position in tile
    const int base0 = HALO + p0 - hk * d;             // first tap of first output

    ull acc[5][PP];
    #pragma unroll
    for (int f = 0; f < 5; f++)
        #pragma unroll
        for (int i = 0; i < PP; i++) acc[f][i] = 0ull;

    #pragma unroll 1
    for (int cp = 0; cp < NCP; cp++){
        // shared window of P+K-1 channel-pair values, stride d (dilated-chain reuse)
        ull xw[PP + K - 1];
        const int b = cp * TILEW + base0;
        #pragma unroll
        for (int j = 0; j < PP + K - 1; j++) xw[j] = xs[swz((uint32_t)(b + j * d))];

        const ull* wbase = ws + cp * K * 6;
        #pragma unroll
        for (int k = 0; k < K; k++){
            const ull* wrow = wbase + k * 6;            // 16B-aligned row of 5 packed weights
            ulonglong2 w01 = *(const ulonglong2*)(wrow);
            ulonglong2 w23 = *(const ulonglong2*)(wrow + 2);
            ull        w4  = wrow[4];
            #pragma unroll
            for (int i = 0; i < PP; i++){
                ull xv = xw[i + k];
                acc[0][i] = fma2(xv, w01.x, acc[0][i]);
                acc[1][i] = fma2(xv, w01.y, acc[1][i]);
                acc[2][i] = fma2(xv, w23.x, acc[2][i]);
                acc[3][i] = fma2(xv, w23.y, acc[3][i]);
                acc[4][i] = fma2(xv, w4,    acc[4][i]);
            }
        }
    }

    // Epilogue: conv = lo+hi (+bias), ppv-count and max per filter
    int cnt[5]; float mx[5];
    #pragma unroll
    for (int f = 0; f < 5; f++){ cnt[f] = 0; mx[f] = __int_as_float(0xff800000); }
    #pragma unroll
    for (int f = 0; f < 5; f++){
        float bb = bias_s[f];
        #pragma unroll
        for (int i = 0; i < PP; i++){
            float lo, hi; unpack2(acc[f][i], lo, hi);
            float v = lo + hi + bb;
            cnt[f] += (v > 0.0f) ? 1 : 0;
            mx[f] = fmaxf(mx[f], v);
        }
    }
    // warp reduce
    #pragma unroll
    for (int off = 16; off > 0; off >>= 1){
        #pragma unroll
        for (int f = 0; f < 5; f++){
            cnt[f] += __shfl_xor_sync(0xffffffffu, cnt[f], off);
            mx[f]   = fmaxf(mx[f], __shfl_xor_sync(0xffffffffu, mx[f], off));
        }
    }
    const int lane = t & 31, w = t >> 5;
    if (lane < 5){
        red[(w * 5 + lane) * 2 + 0] = (float)cnt[lane];
        red[(w * 5 + lane) * 2 + 1] = mx[lane];
    }
    __syncthreads();
    if (t < 5){
        float cs = 0.0f, m = __int_as_float(0xff800000);
        #pragma unroll
        for (int wi = 0; wi < NTH/32; wi++){
            cs += red[(wi * 5 + t) * 2 + 0];
            m = fmaxf(m, red[(wi * 5 + t) * 2 + 1]);
        }
        g_part[(n * NF + fid_base + t) * NTILES + tile] = make_float2(cs, m);
    }
}

__global__ void __launch_bounds__(NTH, 1) rocket_conv_kernel(
    const float* __restrict__ x,
    const float* __restrict__ W7,  const float* __restrict__ b7,
    const float* __restrict__ W9,  const float* __restrict__ b9,
    const float* __restrict__ W11, const float* __restrict__ b11)
{
    extern __shared__ ull sm[];
    ull*   xs     = sm;                              // NCP*TILEW = 8064 ull
    ull*   ws     = sm + NCP * TILEW;                // up to 6*11*6 = 396 ull
    float* red    = (float*)(ws + NCP * 11 * 6);     // 8 warps * 5 * 2
    float* bias_s = red + (NTH/32) * 5 * 2;          // 5 floats

    const int t    = threadIdx.x;
    const int tile = blockIdx.x;
    const int n    = blockIdx.y;
    const int t0   = tile * LT;

    // Fill channel-pair-packed, swizzled x tile (with SAME-padding halo = 160 each side)
    const float* xn = x + (size_t)n * CCH * LL;
    for (int idx = t; idx < NCP * TILEW; idx += NTH){
        int cp = idx / TILEW;
        int p  = idx - cp * TILEW;
        int l  = t0 + p - HALO;
        float lo = 0.0f, hi = 0.0f;
        if (l >= 0 && l < LL){
            lo = xn[(2*cp)     * LL + l];
            hi = xn[(2*cp + 1) * LL + l];
        }
        xs[swz((uint32_t)idx)] = pack2(lo, hi);
    }
    __syncthreads();

    for (int kidx = 0; kidx < 3; kidx++){
        const float* W    = (kidx == 0) ? W7 : (kidx == 1 ? W9 : W11);
        const float* bptr = (kidx == 0) ? b7 : (kidx == 1 ? b9 : b11);
        const int K = 7 + 2 * kidx;
        for (int j = 0; j < 6; j++){          // dilation = 1 << j
            const int fbase = j * 5;
            // Stage packed weights: ws[(cp*K + k)*6 + f] = {W[f][2cp][k], W[f][2cp+1][k]}
            for (int idx = t; idx < NCP * K * 5; idx += NTH){
                int cp = idx / (K * 5);
                int rr = idx - cp * K * 5;
                int k  = rr / 5;
                int f  = rr - k * 5;
                const float* wf = W + (size_t)(fbase + f) * CCH * K;
                float lo = wf[(2*cp)     * K + k];
                float hi = wf[(2*cp + 1) * K + k];
                ws[(cp * K + k) * 6 + f] = pack2(lo, hi);
            }
            if (t < 5) bias_s[t] = bptr[fbase + t];
            __syncthreads();

            const int fid_base = kidx * 30 + j * 5;
            if (K == 7)      do_group<7 >(xs, ws, bias_s, red, j, n, fid_base, tile);
            else if (K == 9) do_group<9 >(xs, ws, bias_s, red, j, n, fid_base, tile);
            else             do_group<11>(xs, ws, bias_s, red, j, n, fid_base, tile);
        }
    }
}

// Combine tile partials, batch-normalize, write (512,180) output.
// One block per feature column; two samples per thread.
__global__ void rocket_finalize_kernel(float* __restrict__ out)
{
    __shared__ float sb[NTH];
    const int col = blockIdx.x;             // 0..179
    const int t   = threadIdx.x;
    const int kidx = col / 60;
    const int rem  = col - kidx * 60;
    const int j    = rem / 10;
    const int p    = (rem % 10) >> 1;
    const int s    = col & 1;               // 0 = ppv, 1 = max
    const int fid  = kidx * 30 + j * 5 + p;

    float raw[2];
    #pragma unroll
    for (int e = 0; e < 2; e++){
        int n = t + e * NTH;
        const float2* pp = &g_part[(n * NF + fid) * NTILES];
        float cs = 0.0f, m = __int_as_float(0xff800000);
        #pragma unroll
        for (int tt = 0; tt < NTILES; tt++){
            float2 v = pp[tt];
            cs += v.x;
            m = fmaxf(m, v.y);
        }
        raw[e] = s ? m : cs * (1.0f / (float)LL);
    }

    // two-pass mean/var over the 512-sample batch (avoids E[x^2]-mu^2 cancellation)
    sb[t] = raw[0] + raw[1];
    __syncthreads();
    for (int stp = NTH/2; stp > 0; stp >>= 1){
        if (t < stp) sb[t] += sb[t + stp];
        __syncthreads();
    }
    float mean = sb[0] * (1.0f / (float)NB);
    __syncthreads();
    float d0 = raw[0] - mean, d1 = raw[1] - mean;
    sb[t] = d0*d0 + d1*d1;
    __syncthreads();
    for (int stp = NTH/2; stp > 0; stp >>= 1){
        if (t < stp) sb[t] += sb[t + stp];
        __syncthreads();
    }
    float var = sb[0] * (1.0f / (float)NB);
    float inv = rsqrtf(var + 1e-5f);
    out[(size_t)t * 180 + col]         = d0 * inv;
    out[(size_t)(t + NTH) * 180 + col] = d1 * inv;
}

extern "C" void kernel_launch(void* const* d_in, const int* in_sizes, int n_in,
                              void* d_out, int out_size)
{
    const float* x   = (const float*)d_in[0];
    const float* W7  = (const float*)d_in[1];
    const float* b7  = (const float*)d_in[2];
    const float* W9  = (const float*)d_in[3];
    const float* b9  = (const float*)d_in[4];
    const float* W11 = (const float*)d_in[5];
    const float* b11 = (const float*)d_in[6];
    float* out = (float*)d_out;

    const int SMEM_BYTES = (NCP * TILEW + NCP * 11 * 6) * 8   // xs + ws
                         + ((NTH/32) * 5 * 2 + 5) * 4 + 16;   // red + bias + pad
    cudaFuncSetAttribute(rocket_conv_kernel,
                         cudaFuncAttributeMaxDynamicSharedMemorySize, SMEM_BYTES);

    dim3 grid(NTILES, NB);
    rocket_conv_kernel<<<grid, NTH, SMEM_BYTES>>>(x, W7, b7, W9, b9, W11, b11);
    rocket_finalize_kernel<<<180, NTH>>>(out);
}

// round 6
// speedup vs baseline: 1.0009x; 1.0006x over previous
#include <cuda_runtime.h>
#include <cstdint>

typedef unsigned long long ull;

#define CCH 12
#define LL 8192
#define NB 512
#define LT 1024
#define HALO 160
#define TILEW (LT + 2*HALO)      // 1344
#define NCP 6                    // channel pairs
#define PP 4                     // outputs per thread per group pass
#define NTH 256
#define NTILES (LL/LT)           // 8
#define NF 90

// Per-(n, filter, tile) partials: x = count(conv+b > 0), y = max(conv+b)
__device__ float2 g_part[NB * NF * NTILES];

// XOR swizzle over 8B shared slots: 16 slots per 128B bank row.
// sw = (row ^ ((row&2)<<2)) & 15 gives the optimal 2-phase LDS.64 pattern
// for every dilation stride d in {1,2,4,8,16,32} with P=4 chains.
__device__ __forceinline__ uint32_t swz(uint32_t idx){
    uint32_t row = idx >> 4;
    uint32_t sw = (row ^ ((row & 2u) << 2)) & 15u;
    return idx ^ sw;
}

__device__ __forceinline__ ull pack2(float lo, float hi){
    ull r; asm("mov.b64 %0, {%1, %2};" : "=l"(r) : "f"(lo), "f"(hi)); return r;
}
__device__ __forceinline__ void unpack2(ull v, float& lo, float& hi){
    asm("mov.b64 {%0, %1}, %2;" : "=f"(lo), "=f"(hi) : "l"(v));
}
// Packed dual fp32 FMA (FFMA2) — full 128-lane fp32 datapath, exact fp32 rounding.
__device__ __forceinline__ ull fma2(ull a, ull b, ull c){
    ull d; asm("fma.rn.f32x2 %0, %1, %2, %3;" : "=l"(d) : "l"(a), "l"(b), "l"(c)); return d;
}

template<int K>
__device__ __forceinline__ void do_group(
    const ull* __restrict__ xs, const ull* __restrict__ ws,
    const float* __restrict__ bias_s, float* red,
    int dlog, int n, int fid_base, int tile)
{
    const int t = threadIdx.x;
    const int d = 1 << dlog;
    const int hk = (K - 1) / 2;
    const int r  = t & (d - 1);
    const int p0 = r + (((t >> dlog) * PP) << dlog);  // chain base position in tile
    const int base0 = HALO + p0 - hk * d;             // first tap of first output

    ull acc[5][PP];
    #pragma unroll
    for (int f = 0; f < 5; f++)
        #pragma unroll
        for (int i = 0; i < PP; i++) acc[f][i] = 0ull;

    #pragma unroll 1
    for (int cp = 0; cp < NCP; cp++){
        // shared window of P+K-1 channel-pair values, stride d (dilated-chain reuse)
        ull xw[PP + K - 1];
        const int b = cp * TILEW + base0;
        #pragma unroll
        for (int j = 0; j < PP + K - 1; j++) xw[j] = xs[swz((uint32_t)(b + j * d))];

        const ull* wbase = ws + cp * K * 6;
        #pragma unroll
        for (int k = 0; k < K; k++){
            const ull* wrow = wbase + k * 6;            // 16B-aligned row of 5 packed weights
            ulonglong2 w01 = *(const ulonglong2*)(wrow);
            ulonglong2 w23 = *(const ulonglong2*)(wrow + 2);
            ull        w4  = wrow[4];
            #pragma unroll
            for (int i = 0; i < PP; i++){
                ull xv = xw[i + k];
                acc[0][i] = fma2(xv, w01.x, acc[0][i]);
                acc[1][i] = fma2(xv, w01.y, acc[1][i]);
                acc[2][i] = fma2(xv, w23.x, acc[2][i]);
                acc[3][i] = fma2(xv, w23.y, acc[3][i]);
                acc[4][i] = fma2(xv, w4,    acc[4][i]);
            }
        }
    }

    // Epilogue: conv = lo+hi (+bias), ppv-count and max per filter
    int cnt[5]; float mx[5];
    #pragma unroll
    for (int f = 0; f < 5; f++){ cnt[f] = 0; mx[f] = __int_as_float(0xff800000); }
    #pragma unroll
    for (int f = 0; f < 5; f++){
        float bb = bias_s[f];
        #pragma unroll
        for (int i = 0; i < PP; i++){
            float lo, hi; unpack2(acc[f][i], lo, hi);
            float v = lo + hi + bb;
            cnt[f] += (v > 0.0f) ? 1 : 0;
            mx[f] = fmaxf(mx[f], v);
        }
    }
    // warp reduce
    #pragma unroll
    for (int off = 16; off > 0; off >>= 1){
        #pragma unroll
        for (int f = 0; f < 5; f++){
            cnt[f] += __shfl_xor_sync(0xffffffffu, cnt[f], off);
            mx[f]   = fmaxf(mx[f], __shfl_xor_sync(0xffffffffu, mx[f], off));
        }
    }
    const int lane = t & 31, w = t >> 5;
    if (lane < 5){
        red[(w * 5 + lane) * 2 + 0] = (float)cnt[lane];
        red[(w * 5 + lane) * 2 + 1] = mx[lane];
    }
    __syncthreads();
    if (t < 5){
        float cs = 0.0f, m = __int_as_float(0xff800000);
        #pragma unroll
        for (int wi = 0; wi < NTH/32; wi++){
            cs += red[(wi * 5 + t) * 2 + 0];
            m = fmaxf(m, red[(wi * 5 + t) * 2 + 1]);
        }
        g_part[(n * NF + fid_base + t) * NTILES + tile] = make_float2(cs, m);
    }
}

__global__ void __launch_bounds__(NTH, 1) rocket_conv_kernel(
    const float* __restrict__ x,
    const float* __restrict__ W7,  const float* __restrict__ b7,
    const float* __restrict__ W9,  const float* __restrict__ b9,
    const float* __restrict__ W11, const float* __restrict__ b11)
{
    extern __shared__ ull sm[];
    ull*   xs     = sm;                              // NCP*TILEW = 8064 ull
    ull*   ws     = sm + NCP * TILEW;                // up to 6*11*6 = 396 ull
    float* red    = (float*)(ws + NCP * 11 * 6);     // 8 warps * 5 * 2
    float* bias_s = red + (NTH/32) * 5 * 2;          // 5 floats

    const int t    = threadIdx.x;
    const int tile = blockIdx.x;
    const int n    = blockIdx.y;
    const int t0   = tile * LT;

    // Fill channel-pair-packed, swizzled x tile (with SAME-padding halo = 160 each side)
    const float* xn = x + (size_t)n * CCH * LL;
    for (int idx = t; idx < NCP * TILEW; idx += NTH){
        int cp = idx / TILEW;
        int p  = idx - cp * TILEW;
        int l  = t0 + p - HALO;
        float lo = 0.0f, hi = 0.0f;
        if (l >= 0 && l < LL){
            lo = xn[(2*cp)     * LL + l];
            hi = xn[(2*cp + 1) * LL + l];
        }
        xs[swz((uint32_t)idx)] = pack2(lo, hi);
    }
    __syncthreads();

    for (int kidx = 0; kidx < 3; kidx++){
        const float* W    = (kidx == 0) ? W7 : (kidx == 1 ? W9 : W11);
        const float* bptr = (kidx == 0) ? b7 : (kidx == 1 ? b9 : b11);
        const int K = 7 + 2 * kidx;
        for (int j = 0; j < 6; j++){          // dilation = 1 << j
            const int fbase = j * 5;
            // Stage packed weights: ws[(cp*K + k)*6 + f] = {W[f][2cp][k], W[f][2cp+1][k]}
            for (int idx = t; idx < NCP * K * 5; idx += NTH){
                int cp = idx / (K * 5);
                int rr = idx - cp * K * 5;
                int k  = rr / 5;
                int f  = rr - k * 5;
                const float* wf = W + (size_t)(fbase + f) * CCH * K;
                float lo = wf[(2*cp)     * K + k];
                float hi = wf[(2*cp + 1) * K + k];
                ws[(cp * K + k) * 6 + f] = pack2(lo, hi);
            }
            if (t < 5) bias_s[t] = bptr[fbase + t];
            __syncthreads();

            const int fid_base = kidx * 30 + j * 5;
            if (K == 7)      do_group<7 >(xs, ws, bias_s, red, j, n, fid_base, tile);
            else if (K == 9) do_group<9 >(xs, ws, bias_s, red, j, n, fid_base, tile);
            else             do_group<11>(xs, ws, bias_s, red, j, n, fid_base, tile);
        }
    }
}

// Combine tile partials, batch-normalize, write (512,180) output.
// One block per feature column; two samples per thread.
__global__ void rocket_finalize_kernel(float* __restrict__ out)
{
    __shared__ float sb[NTH];
    const int col = blockIdx.x;             // 0..179
    const int t   = threadIdx.x;
    const int kidx = col / 60;
    const int rem  = col - kidx * 60;
    const int j    = rem / 10;
    const int p    = (rem % 10) >> 1;
    const int s    = col & 1;               // 0 = ppv, 1 = max
    const int fid  = kidx * 30 + j * 5 + p;

    float raw[2];
    #pragma unroll
    for (int e = 0; e < 2; e++){
        int n = t + e * NTH;
        const float2* pp = &g_part[(n * NF + fid) * NTILES];
        float cs = 0.0f, m = __int_as_float(0xff800000);
        #pragma unroll
        for (int tt = 0; tt < NTILES; tt++){
            float2 v = pp[tt];
            cs += v.x;
            m = fmaxf(m, v.y);
        }
        raw[e] = s ? m : cs * (1.0f / (float)LL);
    }

    // two-pass mean/var over the 512-sample batch (avoids E[x^2]-mu^2 cancellation)
    sb[t] = raw[0] + raw[1];
    __syncthreads();
    for (int stp = NTH/2; stp > 0; stp >>= 1){
        if (t < stp) sb[t] += sb[t + stp];
        __syncthreads();
    }
    float mean = sb[0] * (1.0f / (float)NB);
    __syncthreads();
    float d0 = raw[0] - mean, d1 = raw[1] - mean;
    sb[t] = d0*d0 + d1*d1;
    __syncthreads();
    for (int stp = NTH/2; stp > 0; stp >>= 1){
        if (t < stp) sb[t] += sb[t + stp];
        __syncthreads();
    }
    float var = sb[0] * (1.0f / (float)NB);
    float inv = rsqrtf(var + 1e-5f);
    out[(size_t)t * 180 + col]         = d0 * inv;
    out[(size_t)(t + NTH) * 180 + col] = d1 * inv;
}

extern "C" void kernel_launch(void* const* d_in, const int* in_sizes, int n_in,
                              void* d_out, int out_size)
{
    const float* x   = (const float*)d_in[0];
    const float* W7  = (const float*)d_in[1];
    const float* b7  = (const float*)d_in[2];
    const float* W9  = (const float*)d_in[3];
    const float* b9  = (const float*)d_in[4];
    const float* W11 = (const float*)d_in[5];
    const float* b11 = (const float*)d_in[6];
    float* out = (float*)d_out;

    const int SMEM_BYTES = (NCP * TILEW + NCP * 11 * 6) * 8   // xs + ws
                         + ((NTH/32) * 5 * 2 + 5) * 4 + 16;   // red + bias + pad
    cudaFuncSetAttribute(rocket_conv_kernel,
                         cudaFuncAttributeMaxDynamicSharedMemorySize, SMEM_BYTES);

    dim3 grid(NTILES, NB);
    rocket_conv_kernel<<<grid, NTH, SMEM_BYTES>>>(x, W7, b7, W9, b9, W11, b11);
    rocket_finalize_kernel<<<180, NTH>>>(out);
}